// round 4
// baseline (speedup 1.0000x reference)
#include <cuda_runtime.h>

// 4D transposed conv, stride 2:
//   out[b,co,o1..o4] = bias[co] + sum_{ci,k1..k4 : o=2i+k} x[b,ci,i1..i4] * w[ci,co,k1..k4]
// Scatter form per (o1,o2) block: for each valid (k1,k2)->(i1,i2),
//   GEMM C[(i3,i4),(co,k3,k4)] = sum_ci x[ci,i3,i4]*w[ci,co,k3,k4]
//   out_s[co][2*i3+k3][2*i4+k4] += C   (unconditional; smem atomicAdd resolves overlaps)

#define NKW (81 * 64 * 64)
__device__ float g_wT[NKW];  // [k1,k2,k3,k4][ci][co]

__global__ void transpose_w_kernel(const float* __restrict__ w) {
    int idx = blockIdx.x * blockDim.x + threadIdx.x;
    if (idx < NKW) {
        int kidx = idx >> 12;        // 0..80
        int cico = idx & 4095;       // ci*64+co
        g_wT[idx] = w[cico * 81 + kidx];
    }
}

// smem layout (floats): out_s[32*625]=20000, w_s[9*64*32]=18432, x_s[64*144]=9216
#define SMEM_FLOATS (20000 + 18432 + 9216)

__global__ __launch_bounds__(256, 1) void deconv4d_kernel(
    const float* __restrict__ x, const float* __restrict__ bias,
    float* __restrict__ out)
{
    extern __shared__ float smem[];
    float* out_s = smem;                  // 32 co * 625 (o3*25+o4)
    float* w_s   = smem + 20000;          // [t9=k3*3+k4][ci][co(32)]
    float* x_s   = smem + 20000 + 18432;  // [ci][i3*12+i4]

    const int tid = threadIdx.x;
    const int b  = blockIdx.y;
    const int o1 = blockIdx.x / 25;
    const int o2 = blockIdx.x % 25;

    // valid (k,i) pairs for dims 1 and 2
    int nk1 = 0, k1s[2], i1s[2];
    #pragma unroll
    for (int k = 0; k < 3; k++)
        if (k <= o1 && ((o1 - k) & 1) == 0 && ((o1 - k) >> 1) < 12) {
            k1s[nk1] = k; i1s[nk1] = (o1 - k) >> 1; nk1++;
        }
    int nk2 = 0, k2s[2], i2s[2];
    #pragma unroll
    for (int k = 0; k < 3; k++)
        if (k <= o2 && ((o2 - k) & 1) == 0 && ((o2 - k) >> 1) < 12) {
            k2s[nk2] = k; i2s[nk2] = (o2 - k) >> 1; nk2++;
        }

    for (int coh = 0; coh < 2; coh++) {
        const int co0 = coh * 32;

        // init accumulation buffer with bias
        for (int i = tid; i < 20000; i += 256)
            out_s[i] = bias[co0 + i / 625];
        __syncthreads();

        for (int c1 = 0; c1 < nk1; c1++) {
            for (int c2 = 0; c2 < nk2; c2++) {
                const int i1 = i1s[c1], i2 = i2s[c2];
                const int kbase = (k1s[c1] * 3 + k2s[c2]) * 9;

                // load x slab [64 ci][144] (contiguous per ci)
                for (int t = tid; t < 2304; t += 256) {
                    int ci = t / 36, r = t - ci * 36;
                    const float4* src = (const float4*)(x +
                        ((size_t)((b * 64 + ci) * 144 + i1 * 12 + i2)) * 144);
                    ((float4*)x_s)[t] = src[r];
                }
                // load weight slab [9 taps][64 ci][32 co]
                for (int t = tid; t < 4608; t += 256) {
                    int c4 = t & 7, ci = (t >> 3) & 63, t9 = t >> 9;
                    ((float4*)w_s)[t] = *(const float4*)(g_wT +
                        (kbase + t9) * 4096 + ci * 64 + co0 + c4 * 4);
                }
                __syncthreads();

                // 3 chunks of thread tiles: tile = [6 spatial x 1 co x 9 taps]
                for (int chunk = 0; chunk < 3; chunk++) {
                    const int cog = tid & 31;                 // lane -> co (coalesced w LDS)
                    const int mg  = chunk * 8 + (tid >> 5);   // warp-uniform -> x broadcast
                    const int i3  = mg >> 1;
                    const int i40 = (mg & 1) * 6;

                    float acc[54];
                    #pragma unroll
                    for (int i = 0; i < 54; i++) acc[i] = 0.0f;

                    const float* xb = x_s + i3 * 12 + i40;
                    for (int ci = 0; ci < 64; ci++) {
                        const float* xr = xb + ci * 144;
                        float xv[6];
                        #pragma unroll
                        for (int h = 0; h < 3; h++) {
                            float2 t2 = *(const float2*)(xr + 2 * h);
                            xv[2 * h] = t2.x; xv[2 * h + 1] = t2.y;
                        }
                        #pragma unroll
                        for (int t9 = 0; t9 < 9; t9++) {
                            float wv = w_s[(t9 * 64 + ci) * 32 + cog];
                            #pragma unroll
                            for (int mi = 0; mi < 6; mi++)
                                acc[t9 * 6 + mi] = fmaf(xv[mi], wv, acc[t9 * 6 + mi]);
                        }
                    }

                    // scatter: o3 = 2*i3+k3, o4 = 2*(i40+mi)+k4 (always in range)
                    float* os = out_s + cog * 625;
                    #pragma unroll
                    for (int k3 = 0; k3 < 3; k3++) {
                        const int o3 = 2 * i3 + k3;
                        #pragma unroll
                        for (int k4 = 0; k4 < 3; k4++) {
                            const int t9 = k3 * 3 + k4;
                            #pragma unroll
                            for (int mi = 0; mi < 6; mi++) {
                                const int o4 = 2 * (i40 + mi) + k4;
                                atomicAdd(&os[o3 * 25 + o4], acc[t9 * 6 + mi]);
                            }
                        }
                    }
                }
                __syncthreads();  // atoms drained; safe to reload w_s/x_s
            }
        }

        // write this co-half (coalesced along o3*25+o4)
        for (int i = tid; i < 20000; i += 256) {
            int co = i / 625, r = i - co * 625;
            out[(size_t)(b * 64 + co0 + co) * 390625 +
                o1 * 15625 + o2 * 625 + r] = out_s[i];
        }
        __syncthreads();  // before re-init of out_s for next half
    }
}

extern "C" void kernel_launch(void* const* d_in, const int* in_sizes, int n_in,
                              void* d_out, int out_size) {
    const float* x    = (const float*)d_in[0];
    const float* w    = (const float*)d_in[1];
    const float* bias = (const float*)d_in[2];
    float* out = (float*)d_out;

    (void)in_sizes; (void)n_in; (void)out_size;

    static int attr_done = 0;
    // idempotent, deterministic; required for >48KB dynamic smem
    cudaFuncSetAttribute(deconv4d_kernel,
                         cudaFuncAttributeMaxDynamicSharedMemorySize,
                         SMEM_FLOATS * sizeof(float));
    (void)attr_done;

    transpose_w_kernel<<<(NKW + 255) / 256, 256>>>(w);

    dim3 grid(625, 4);
    deconv4d_kernel<<<grid, 256, SMEM_FLOATS * sizeof(float)>>>(x, bias, out);
}

// round 5
// speedup vs baseline: 1.1454x; 1.1454x over previous
#include <cuda_runtime.h>

// 4D transposed conv, stride 2:
//   out[b,co,o1..o4] = bias[co] + sum_{ci,k1..k4 : o=2i+k} x[b,ci,i1..i4] * w[ci,co,k1..k4]
// Per (b,o1,o2) block: for each valid (k1,k2)->(i1,i2) combo,
//   GEMM C[(i3,i4),(co,k3,k4)] = sum_ci x[ci,i3,i4]*w[ci,co,k3,k4]   (fma.rn.f32x2 mainloop)
//   scatter out_s[co][2*i3+k3][2*i4+k4] += C in tap-parity rounds (conflict-free, no atomics)

#define NKW (81 * 64 * 64)
__device__ float g_wT[NKW];  // [k1,k2,k3,k4][ci][co]

__global__ void transpose_w_kernel(const float* __restrict__ w) {
    int idx = blockIdx.x * blockDim.x + threadIdx.x;
    if (idx < NKW) {
        int kidx = idx >> 12;        // 0..80
        int cico = idx & 4095;       // ci*64+co
        g_wT[idx] = w[cico * 81 + kidx];
    }
}

// smem layout (floats): out_s[32*625]=20000, w_s[9*64*32]=18432, x_s[64*144]=9216
#define SMEM_FLOATS (20000 + 18432 + 9216)

typedef unsigned long long u64;

__device__ __forceinline__ void fma2(u64& d, u64 a, u64 b) {
    asm("fma.rn.f32x2 %0, %1, %2, %0;" : "+l"(d) : "l"(a), "l"(b));
}
__device__ __forceinline__ u64 pack2(float w) {
    u64 r;
    asm("mov.b64 %0, {%1, %1};" : "=l"(r) : "f"(w));
    return r;
}
__device__ __forceinline__ void unpack2(u64 v, float& lo, float& hi) {
    unsigned int l, h;
    asm("mov.b64 {%0, %1}, %2;" : "=r"(l), "=r"(h) : "l"(v));
    lo = __uint_as_float(l);
    hi = __uint_as_float(h);
}

__global__ __launch_bounds__(256, 1) void deconv4d_kernel(
    const float* __restrict__ x, const float* __restrict__ bias,
    float* __restrict__ out)
{
    extern __shared__ float smem[];
    float* out_s = smem;                  // 32 co * 625 (o3*25+o4)
    float* w_s   = smem + 20000;          // [t9=k3*3+k4][ci][co(32)]
    float* x_s   = smem + 20000 + 18432;  // [ci][i3*12+i4]

    const int tid = threadIdx.x;
    const int b  = blockIdx.y;
    const int o1 = blockIdx.x / 25;
    const int o2 = blockIdx.x % 25;

    // valid (k,i) pairs for dims 1 and 2
    int nk1 = 0, k1s[2], i1s[2];
    #pragma unroll
    for (int k = 0; k < 3; k++)
        if (k <= o1 && ((o1 - k) & 1) == 0 && ((o1 - k) >> 1) < 12) {
            k1s[nk1] = k; i1s[nk1] = (o1 - k) >> 1; nk1++;
        }
    int nk2 = 0, k2s[2], i2s[2];
    #pragma unroll
    for (int k = 0; k < 3; k++)
        if (k <= o2 && ((o2 - k) & 1) == 0 && ((o2 - k) >> 1) < 12) {
            k2s[nk2] = k; i2s[nk2] = (o2 - k) >> 1; nk2++;
        }

    // Tap rounds: taps grouped so that within a round no two taps share both
    // k3-parity and k4-parity (=> conflict-free scatter within a round).
    // t9 = k3*3+k4. Rounds: [0,1,3,4] [2,7,5] [6] [8]
    const int tap_order[9]  = {0, 1, 3, 4, 2, 7, 5, 6, 8};
    const int round_start[5] = {0, 4, 7, 8, 9};

    for (int coh = 0; coh < 2; coh++) {
        const int co0 = coh * 32;

        // init accumulation buffer with bias
        for (int i = tid; i < 20000; i += 256)
            out_s[i] = bias[co0 + i / 625];
        __syncthreads();

        for (int c1 = 0; c1 < nk1; c1++) {
            for (int c2 = 0; c2 < nk2; c2++) {
                const int i1 = i1s[c1], i2 = i2s[c2];
                const int kbase = (k1s[c1] * 3 + k2s[c2]) * 9;

                // load x slab [64 ci][144] (contiguous per ci)
                for (int t = tid; t < 2304; t += 256) {
                    int ci = t / 36, r = t - ci * 36;
                    const float4* src = (const float4*)(x +
                        ((size_t)((b * 64 + ci) * 144 + i1 * 12 + i2)) * 144);
                    ((float4*)x_s)[t] = src[r];
                }
                // load weight slab [9 taps][64 ci][32 co]
                for (int t = tid; t < 4608; t += 256) {
                    int c4 = t & 7, ci = (t >> 3) & 63, t9 = t >> 9;
                    ((float4*)w_s)[t] = *(const float4*)(g_wT +
                        (kbase + t9) * 4096 + ci * 64 + co0 + c4 * 4);
                }
                __syncthreads();

                // 3 chunks of thread tiles: tile = [6 spatial x 1 co x 9 taps]
                for (int chunk = 0; chunk < 3; chunk++) {
                    const int cog = tid & 31;                 // lane -> co (coalesced LDS)
                    const int mg  = chunk * 8 + (tid >> 5);   // warp-uniform -> x broadcast
                    const int i3  = mg >> 1;
                    const int i40 = (mg & 1) * 6;

                    u64 acc[27];
                    #pragma unroll
                    for (int i = 0; i < 27; i++) acc[i] = 0ULL;

                    const float* xb = x_s + i3 * 12 + i40;
                    const float* wb = w_s + cog;
                    #pragma unroll 4
                    for (int ci = 0; ci < 64; ci++) {
                        const u64* xp = (const u64*)(xb + ci * 144);
                        u64 xv0 = xp[0], xv1 = xp[1], xv2 = xp[2];
                        const float* wr = wb + ci * 32;
                        #pragma unroll
                        for (int t9 = 0; t9 < 9; t9++) {
                            u64 w2 = pack2(wr[t9 * 2048]);
                            fma2(acc[t9 * 3 + 0], xv0, w2);
                            fma2(acc[t9 * 3 + 1], xv1, w2);
                            fma2(acc[t9 * 3 + 2], xv2, w2);
                        }
                    }

                    // conflict-free scatter in 4 barrier-separated tap rounds
                    float* osb = out_s + cog * 625;
                    #pragma unroll
                    for (int r = 0; r < 4; r++) {
                        __syncthreads();
                        #pragma unroll
                        for (int t = round_start[r]; t < round_start[r + 1]; t++) {
                            const int t9 = tap_order[t];
                            const int k3 = t9 / 3, k4 = t9 % 3;
                            float* os = osb + (2 * i3 + k3) * 25 + k4;
                            #pragma unroll
                            for (int h = 0; h < 3; h++) {
                                float lo, hi;
                                unpack2(acc[t9 * 3 + h], lo, hi);
                                const int base = 2 * (i40 + 2 * h);
                                os[base]     += lo;   // o4 = 2*(i40+2h)+k4
                                os[base + 2] += hi;   // o4 = 2*(i40+2h+1)+k4
                            }
                        }
                    }
                }
                __syncthreads();  // scatter of last round drained; safe to reload slabs
            }
        }

        // write this co-half (coalesced along o3*25+o4)
        for (int i = tid; i < 20000; i += 256) {
            int co = i / 625, r = i - co * 625;
            out[(size_t)(b * 64 + co0 + co) * 390625 +
                o1 * 15625 + o2 * 625 + r] = out_s[i];
        }
        __syncthreads();  // before re-init of out_s for next half
    }
}

extern "C" void kernel_launch(void* const* d_in, const int* in_sizes, int n_in,
                              void* d_out, int out_size) {
    const float* x    = (const float*)d_in[0];
    const float* w    = (const float*)d_in[1];
    const float* bias = (const float*)d_in[2];
    float* out = (float*)d_out;

    (void)in_sizes; (void)n_in; (void)out_size;

    // idempotent, deterministic; required for >48KB dynamic smem
    cudaFuncSetAttribute(deconv4d_kernel,
                         cudaFuncAttributeMaxDynamicSharedMemorySize,
                         SMEM_FLOATS * sizeof(float));

    transpose_w_kernel<<<(NKW + 255) / 256, 256>>>(w);

    dim3 grid(625, 4);
    deconv4d_kernel<<<grid, 256, SMEM_FLOATS * sizeof(float)>>>(x, bias, out);
}

// round 6
// speedup vs baseline: 1.5506x; 1.3538x over previous
#include <cuda_runtime.h>

// 4D transposed conv, stride 2:
//   out[b,co,o1..o4] = bias[co] + sum_{ci,k1..k4 : o=2i+k} x[b,ci,i1..i4] * w[ci,co,k1..k4]
// Per (b,o1,o2) block: for each valid (k1,k2)->(i1,i2) combo,
//   GEMM C[(i3,i4),(co,k3,k4)] = sum_ci x[ci,i3,i4]*w[ci,co,k3,k4]   (fma.rn.f32x2)
//   scatter out_s[co][2*i3+k3][2*i4+k4] += C
// Warp w owns i3 row w (12 warps = 12 rows). Scatter needs only 2 barrier
// rounds: k3 in {0,1} touches o3 in {2w,2w+1} (disjoint across warps);
// k3=2 touches o3=2w+2 (disjoint across warps, but collides with neighbor's
// round-A rows -> one barrier between).

#define NKW (81 * 64 * 64)
__device__ float g_wT[NKW];  // [k1,k2,k3,k4][ci][co]

__global__ void transpose_w_kernel(const float* __restrict__ w) {
    int idx = blockIdx.x * blockDim.x + threadIdx.x;
    if (idx < NKW) {
        int kidx = idx >> 12;        // 0..80
        int cico = idx & 4095;       // ci*64+co
        g_wT[idx] = w[cico * 81 + kidx];
    }
}

// smem (floats): out_s[32*625]=20000, w_s[9*64*32]=18432, x_s[64][12][16]=12288
#define WS_OFF 20000
#define XS_OFF 38432
#define SMEM_FLOATS 50720

typedef unsigned long long u64;

__device__ __forceinline__ void fma2(u64& d, u64 a, u64 b) {
    asm("fma.rn.f32x2 %0, %1, %2, %0;" : "+l"(d) : "l"(a), "l"(b));
}
__device__ __forceinline__ u64 pack2(float w) {
    u64 r;
    asm("mov.b64 %0, {%1, %1};" : "=l"(r) : "f"(w));
    return r;
}
__device__ __forceinline__ void unpack2(u64 v, float& lo, float& hi) {
    unsigned int l, h;
    asm("mov.b64 {%0, %1}, %2;" : "=r"(l), "=r"(h) : "l"(v));
    lo = __uint_as_float(l);
    hi = __uint_as_float(h);
}

__global__ __launch_bounds__(384, 1) void deconv4d_kernel(
    const float* __restrict__ x, const float* __restrict__ bias,
    float* __restrict__ out)
{
    extern __shared__ float smem[];
    float* out_s = smem;               // [32 co][25 o3][25 o4]
    float* w_s   = smem + WS_OFF;      // [t9=k3*3+k4][ci][co(32)]
    float* x_s   = smem + XS_OFF;      // [ci][i3][16] (12 used, padded for LDS.128)

    const int tid  = threadIdx.x;
    const int lane = tid & 31;         // -> co within half
    const int wid  = tid >> 5;         // -> i3 row (0..11)
    const int b  = blockIdx.y;
    const int o1 = blockIdx.x / 25;
    const int o2 = blockIdx.x % 25;

    // valid (k,i) pairs for dims 1 and 2
    int nk1 = 0, k1s[2], i1s[2];
    #pragma unroll
    for (int k = 0; k < 3; k++)
        if (k <= o1 && ((o1 - k) & 1) == 0 && ((o1 - k) >> 1) < 12) {
            k1s[nk1] = k; i1s[nk1] = (o1 - k) >> 1; nk1++;
        }
    int nk2 = 0, k2s[2], i2s[2];
    #pragma unroll
    for (int k = 0; k < 3; k++)
        if (k <= o2 && ((o2 - k) & 1) == 0 && ((o2 - k) >> 1) < 12) {
            k2s[nk2] = k; i2s[nk2] = (o2 - k) >> 1; nk2++;
        }

    for (int coh = 0; coh < 2; coh++) {
        const int co0 = coh * 32;

        // init accumulation buffer with bias
        for (int i = tid; i < 20000; i += 384)
            out_s[i] = bias[co0 + i / 625];
        __syncthreads();

        for (int c1 = 0; c1 < nk1; c1++) {
            for (int c2 = 0; c2 < nk2; c2++) {
                const int i1 = i1s[c1], i2 = i2s[c2];
                const int kbase = (k1s[c1] * 3 + k2s[c2]) * 9;

                // x slab [64 ci][12 i3][16 pad] as float2 (rows 12 floats, padded to 16)
                for (int t = tid; t < 4608; t += 384) {
                    int ci = t / 72, r = t - ci * 72;
                    int i3 = r / 6,  j = r - i3 * 6;
                    size_t sb = ((size_t)((b * 64 + ci) * 144 + i1 * 12 + i2)) * 72;
                    ((float2*)x_s)[ci * 96 + i3 * 8 + j] =
                        ((const float2*)x)[sb + i3 * 6 + j];
                }
                // w slab [9 taps][64 ci][32 co]
                for (int t = tid; t < 4608; t += 384) {
                    int c4 = t & 7, ci = (t >> 3) & 63, t9 = t >> 9;
                    ((float4*)w_s)[t] = *(const float4*)(g_wT +
                        (kbase + t9) * 4096 + ci * 64 + co0 + c4 * 4);
                }
                __syncthreads();

                // mainloop: warp tile = 12 spatial (i3=wid, all i4) x 32 co x 9 taps
                u64 acc[54];
                #pragma unroll
                for (int i = 0; i < 54; i++) acc[i] = 0ULL;

                const float* wb = w_s + lane;
                #pragma unroll 2
                for (int ci = 0; ci < 64; ci++) {
                    const ulonglong2* xp =
                        (const ulonglong2*)(x_s + ci * 192 + wid * 16);
                    ulonglong2 p0 = xp[0], p1 = xp[1], p2 = xp[2];
                    u64 xv0 = p0.x, xv1 = p0.y, xv2 = p1.x;
                    u64 xv3 = p1.y, xv4 = p2.x, xv5 = p2.y;
                    const float* wr = wb + ci * 32;
                    #pragma unroll
                    for (int t9 = 0; t9 < 9; t9++) {
                        u64 w2 = pack2(wr[t9 * 2048]);
                        fma2(acc[t9 * 6 + 0], xv0, w2);
                        fma2(acc[t9 * 6 + 1], xv1, w2);
                        fma2(acc[t9 * 6 + 2], xv2, w2);
                        fma2(acc[t9 * 6 + 3], xv3, w2);
                        fma2(acc[t9 * 6 + 4], xv4, w2);
                        fma2(acc[t9 * 6 + 5], xv5, w2);
                    }
                }

                // scatter, 2 conflict-free rounds
                float* osb = out_s + lane * 625;
                // Round A: k3 in {0,1} -> o3 in {2*wid, 2*wid+1}
                #pragma unroll
                for (int k3 = 0; k3 < 2; k3++) {
                    float* row = osb + (2 * wid + k3) * 25;
                    #pragma unroll
                    for (int k4 = 0; k4 < 3; k4++) {
                        const int t9 = k3 * 3 + k4;
                        #pragma unroll
                        for (int h = 0; h < 6; h++) {
                            float lo, hi;
                            unpack2(acc[t9 * 6 + h], lo, hi);
                            row[4 * h + k4]     += lo;  // o4 = 2*(2h)+k4
                            row[4 * h + 2 + k4] += hi;  // o4 = 2*(2h+1)+k4
                        }
                    }
                }
                __syncthreads();
                // Round B: k3 = 2 -> o3 = 2*wid+2
                {
                    float* row = osb + (2 * wid + 2) * 25;
                    #pragma unroll
                    for (int k4 = 0; k4 < 3; k4++) {
                        const int t9 = 6 + k4;
                        #pragma unroll
                        for (int h = 0; h < 6; h++) {
                            float lo, hi;
                            unpack2(acc[t9 * 6 + h], lo, hi);
                            row[4 * h + k4]     += lo;
                            row[4 * h + 2 + k4] += hi;
                        }
                    }
                }
                __syncthreads();  // scatter drained; safe to reload slabs / write out
            }
        }

        // write this co-half (coalesced along o3*25+o4)
        for (int i = tid; i < 20000; i += 384) {
            int co = i / 625, r = i - co * 625;
            out[(size_t)(b * 64 + co0 + co) * 390625 +
                o1 * 15625 + o2 * 625 + r] = out_s[i];
        }
        __syncthreads();  // before re-init of out_s for next half
    }
}

extern "C" void kernel_launch(void* const* d_in, const int* in_sizes, int n_in,
                              void* d_out, int out_size) {
    const float* x    = (const float*)d_in[0];
    const float* w    = (const float*)d_in[1];
    const float* bias = (const float*)d_in[2];
    float* out = (float*)d_out;

    (void)in_sizes; (void)n_in; (void)out_size;

    // idempotent, deterministic; required for >48KB dynamic smem
    cudaFuncSetAttribute(deconv4d_kernel,
                         cudaFuncAttributeMaxDynamicSharedMemorySize,
                         SMEM_FLOATS * sizeof(float));

    transpose_w_kernel<<<(NKW + 255) / 256, 256>>>(w);

    dim3 grid(625, 4);
    deconv4d_kernel<<<grid, 384, SMEM_FLOATS * sizeof(float)>>>(x, bias, out);
}